// round 16
// baseline (speedup 1.0000x reference)
#include <cuda_runtime.h>
#include <cuda_fp16.h>
#include <math.h>
#include <stdint.h>

#define BB 4
#define SS 4096
#define CCH 128
#define HIDN 256
#define NROWS (BB*SS)      /* 16384 */
#define SQALPHA 0.6005612044f   /* sqrt(0.25 * log2(e)) */

/* ------------ scratch (device globals: allocation-free rule) ------------- */
__device__ float  g_t   [NROWS*CCH];
__device__ __half g_xl  [NROWS*CCH];
__device__ __half g_q   [NROWS*CCH];
__device__ __half g_k   [NROWS*CCH];
__device__ __half g_v   [NROWS*CCH];
__device__ __half g_vT  [NROWS*CCH];
__device__ float  g_y   [NROWS*CCH];
__device__ __half g_h   [NROWS*HIDN];
__device__ __half g_scoresh[(size_t)BB*SS*SS];   /* 134 MB fp16 scores (log2 dom) */
__device__ float  g_psum[32*NROWS];               /* per-m-tile column sums */
__device__ __half g_offh[NROWS];                  /* -log2(l) as half */
__device__ float  g_aop [4*NROWS*CCH];            /* split-K AV partials */
__device__ __half g_wqkvT[3*CCH*CCH];
__device__ __half g_woT [CCH*CCH];
__device__ __half g_w1T [CCH*HIDN];
__device__ __half g_w2T [CCH*HIDN];

/* ------------------------- helpers --------------------------------------- */
__device__ __forceinline__ uint32_t smem_u32(const void* p) {
    uint32_t a;
    asm("{ .reg .u64 t; cvta.to.shared.u64 t, %1; cvt.u32.u64 %0, t; }"
        : "=r"(a) : "l"(p));
    return a;
}

__device__ __forceinline__ uint32_t h2ex2(uint32_t x) {
    uint32_t r;
    asm("ex2.approx.f16x2 %0, %1;" : "=r"(r) : "r"(x));
    return r;
}

__device__ __forceinline__ float gelu_exact(float v) {
    return 0.5f * v * (1.0f + erff(v * 0.70710678118654752f));
}

__device__ __forceinline__ void mma_f16(
    float* d, uint32_t a0, uint32_t a1, uint32_t a2, uint32_t a3,
    uint32_t b0, uint32_t b1)
{
    asm volatile(
        "mma.sync.aligned.m16n8k16.row.col.f32.f16.f16.f32 "
        "{%0,%1,%2,%3}, {%4,%5,%6,%7}, {%8,%9}, {%0,%1,%2,%3};"
        : "+f"(d[0]), "+f"(d[1]), "+f"(d[2]), "+f"(d[3])
        : "r"(a0), "r"(a1), "r"(a2), "r"(a3), "r"(b0), "r"(b1));
}

__device__ __forceinline__ void ldsm4(uint32_t& r0, uint32_t& r1,
                                      uint32_t& r2, uint32_t& r3, uint32_t addr)
{
    asm volatile("ldmatrix.sync.aligned.m8n8.x4.shared.b16 {%0,%1,%2,%3}, [%4];"
                 : "=r"(r0), "=r"(r1), "=r"(r2), "=r"(r3) : "r"(addr));
}

/* --------------------- fused transpose + LN1 ------------------------------ */
__global__ __launch_bounds__(1024) void ln1_fused(
    const float* __restrict__ x, const float* __restrict__ w,
    const float* __restrict__ b, float* __restrict__ tout,
    __half* __restrict__ xl)
{
    __shared__ float sm[32][133];
    int z  = blockIdx.y;
    int s0 = blockIdx.x * 32;
    int sx = threadIdx.x;
    int cy = threadIdx.y;
    const float* xb = x + (size_t)z * CCH * SS;
    #pragma unroll
    for (int i = 0; i < 4; i++) {
        int c = cy + 32 * i;
        sm[sx][c] = xb[(size_t)c * SS + s0 + sx];
    }
    __syncthreads();
    int row  = threadIdx.y;
    int lane = threadIdx.x;
    float4 v;
    v.x = sm[row][lane * 4 + 0];
    v.y = sm[row][lane * 4 + 1];
    v.z = sm[row][lane * 4 + 2];
    v.w = sm[row][lane * 4 + 3];
    float s = v.x + v.y + v.z + v.w;
    #pragma unroll
    for (int o = 16; o > 0; o >>= 1) s += __shfl_xor_sync(0xffffffffu, s, o);
    float mu = s * (1.0f / 128.0f);
    float dx = v.x - mu, dy = v.y - mu, dz = v.z - mu, dw = v.w - mu;
    float q = dx*dx + dy*dy + dz*dz + dw*dw;
    #pragma unroll
    for (int o = 16; o > 0; o >>= 1) q += __shfl_xor_sync(0xffffffffu, q, o);
    float rstd = rsqrtf(q * (1.0f / 128.0f) + 1e-5f);
    float4 wv = *(const float4*)&w[lane * 4];
    float4 bv = *(const float4*)&b[lane * 4];
    size_t base = ((size_t)z * SS + s0 + row) * CCH + lane * 4;
    *(float4*)&tout[base] = v;
    __half2 h01 = __floats2half2_rn(dx * rstd * wv.x + bv.x, dy * rstd * wv.y + bv.y);
    __half2 h23 = __floats2half2_rn(dz * rstd * wv.z + bv.z, dw * rstd * wv.w + bv.w);
    uint2 o2; o2.x = *(uint32_t*)&h01; o2.y = *(uint32_t*)&h23;
    *(uint2*)&xl[base] = o2;
}

/* half -> half, transposed, per batch (v -> vT) */
__global__ __launch_bounds__(1024) void transpose_h(
    const __half* __restrict__ src, __half* __restrict__ dst, int R, int Cc)
{
    __shared__ __half tile[32][34];
    size_t zo = (size_t)blockIdx.z * R * Cc;
    int c0 = blockIdx.x * 32, r0 = blockIdx.y * 32;
    int x = threadIdx.x, y = threadIdx.y;
    tile[y][x] = src[zo + (size_t)(r0 + y) * Cc + c0 + x];
    __syncthreads();
    dst[zo + (size_t)(c0 + y) * R + r0 + x] = tile[x][y];
}

/* all six weight transposes (f32 -> f16, W[K,N] -> W^T[N,K]) in ONE launch */
__global__ __launch_bounds__(1024) void transpose_weights(
    const float* __restrict__ wq, const float* __restrict__ wk,
    const float* __restrict__ wv, const float* __restrict__ wo,
    const float* __restrict__ w1, const float* __restrict__ w2,
    __half* __restrict__ dqkv, __half* __restrict__ dwo,
    __half* __restrict__ dw1, __half* __restrict__ dw2)
{
    const float* src;
    __half* dst;
    int R, Cc;
    switch (blockIdx.z) {
        case 0:  src = wq; dst = dqkv;               R = CCH;  Cc = CCH;  break;
        case 1:  src = wk; dst = dqkv + CCH*CCH;     R = CCH;  Cc = CCH;  break;
        case 2:  src = wv; dst = dqkv + 2*CCH*CCH;   R = CCH;  Cc = CCH;  break;
        case 3:  src = wo; dst = dwo;                R = CCH;  Cc = CCH;  break;
        case 4:  src = w1; dst = dw1;                R = CCH;  Cc = HIDN; break;
        default: src = w2; dst = dw2;                R = HIDN; Cc = CCH;  break;
    }
    int c0 = blockIdx.x * 32, r0 = blockIdx.y * 32;
    if (c0 >= Cc || r0 >= R) return;
    __shared__ float tile[32][33];
    int x = threadIdx.x, y = threadIdx.y;
    tile[y][x] = src[(size_t)(r0 + y) * Cc + c0 + x];
    __syncthreads();
    dst[(size_t)(c0 + y) * R + r0 + x] = __float2half_rn(tile[x][y]);
}

/* reduce 32 column-sum partials -> noff half = -log2(l) */
__global__ __launch_bounds__(256) void noff_k(
    const float* __restrict__ psum, __half* __restrict__ offh) {
    int i = blockIdx.x * 256 + threadIdx.x;
    float l = 0.0f;
    #pragma unroll
    for (int my = 0; my < 32; my++) l += psum[(size_t)my * NROWS + i];
    offh[i] = __float2half_rn(-log2f(l));
}

/* ---------------- GEMM geometry ------------------------------------------- */
#define LDH 40
#define HBUF (128*LDH)

__device__ __forceinline__ void compute_chunk(
    float acc[2][8][4], uint32_t abase, uint32_t bbase, int wm, int wn, int lane)
{
    int rA = (lane & 7) + ((lane >> 3) & 1) * 8;
    int cA = (lane >> 4) * 8;
    #pragma unroll
    for (int s = 0; s < 2; s++) {
        uint32_t af[2][4];
        #pragma unroll
        for (int mt = 0; mt < 2; mt++) {
            uint32_t addr = abase +
                ((uint32_t)((wm * 32 + mt * 16 + rA) * LDH + s * 16 + cA) << 1);
            ldsm4(af[mt][0], af[mt][1], af[mt][2], af[mt][3], addr);
        }
        #pragma unroll
        for (int ntp = 0; ntp < 4; ntp++) {
            uint32_t bf0, bf1, bf2, bf3;
            uint32_t addr = bbase +
                ((uint32_t)((wn * 64 + ntp * 16 + rA) * LDH + s * 16 + cA) << 1);
            ldsm4(bf0, bf1, bf2, bf3, addr);
            #pragma unroll
            for (int mt = 0; mt < 2; mt++) {
                mma_f16(acc[mt][ntp * 2 + 0],
                        af[mt][0], af[mt][1], af[mt][2], af[mt][3], bf0, bf2);
                mma_f16(acc[mt][ntp * 2 + 1],
                        af[mt][0], af[mt][1], af[mt][2], af[mt][3], bf1, bf3);
            }
        }
    }
}

#define GEMM_PROLOGUE()                                                         \
    int t = threadIdx.x;                                                        \
    int wid = t >> 5, lane = t & 31;                                            \
    int wm = wid & 3, wn = wid >> 2;                                            \
    int gid = lane >> 2, tig = lane & 3;                                        \
    float acc[2][8][4];                                                         \
    _Pragma("unroll")                                                           \
    for (int mt = 0; mt < 2; mt++)                                              \
        _Pragma("unroll")                                                       \
        for (int nt = 0; nt < 8; nt++)                                          \
            _Pragma("unroll")                                                   \
            for (int e = 0; e < 4; e++) acc[mt][nt][e] = 0.0f;

/* ------------- MLP1: h = gelu(A @ B^T + bias), half out ------------------- */
__global__ __launch_bounds__(256, 2) void gemm_mlp1(
    const __half* __restrict__ A, const __half* __restrict__ Bm,
    const float* __restrict__ bias, __half* __restrict__ Cout, int N, int K)
{
    __shared__ __half As[2][HBUF];
    __shared__ __half Bs[2][HBUF];
    GEMM_PROLOGUE();
    int m0 = blockIdx.y * 128;
    int n0 = blockIdx.x * 128;
    int nch = K >> 5;

    uint4 ra[2], rb[2];
    auto ldg_chunk = [&](int c) {
        int k0 = c << 5;
        #pragma unroll
        for (int i = 0; i < 2; i++) {
            int idx = i * 256 + t;
            int r = idx >> 2, c8 = idx & 3;
            ra[i] = *(const uint4*)&A[(size_t)(m0 + r) * K + k0 + c8 * 8];
            rb[i] = *(const uint4*)&Bm[(size_t)(n0 + r) * K + k0 + c8 * 8];
        }
    };
    auto st_chunk = [&](int buf) {
        #pragma unroll
        for (int i = 0; i < 2; i++) {
            int idx = i * 256 + t;
            int r = idx >> 2, c8 = idx & 3;
            *(uint4*)&As[buf][r * LDH + c8 * 8] = ra[i];
            *(uint4*)&Bs[buf][r * LDH + c8 * 8] = rb[i];
        }
    };

    ldg_chunk(0); st_chunk(0); __syncthreads();
    for (int c = 0; c < nch; c++) {
        if (c + 1 < nch) ldg_chunk(c + 1);
        compute_chunk(acc, smem_u32(&As[c & 1][0]), smem_u32(&Bs[c & 1][0]),
                      wm, wn, lane);
        if (c + 1 < nch) { st_chunk((c + 1) & 1); __syncthreads(); }
    }

    int rbase = m0 + wm * 32 + gid;
    int cbase = n0 + wn * 64 + tig * 2;
    #pragma unroll
    for (int mt = 0; mt < 2; mt++)
        #pragma unroll
        for (int hh = 0; hh < 2; hh++) {
            int row = rbase + mt * 16 + hh * 8;
            size_t rowo = (size_t)row * N;
            #pragma unroll
            for (int nt = 0; nt < 8; nt++) {
                int col = cbase + nt * 8;
                float u0 = gelu_exact(acc[mt][nt][hh*2+0] + __ldg(&bias[col]));
                float u1 = gelu_exact(acc[mt][nt][hh*2+1] + __ldg(&bias[col+1]));
                __half2 h2 = __floats2half2_rn(u0, u1);
                *(__half2*)&Cout[rowo + col] = h2;
            }
        }
}

/* ------- wo GEMM: y = (sum AV partials) @ wo^T + bo + t, LN2 fused -------- */
__global__ __launch_bounds__(256, 2) void gemm_wo(
    const float* __restrict__ P, const __half* __restrict__ Bm,
    const float* __restrict__ bias, const float* __restrict__ res,
    const float* __restrict__ ln2w, const float* __restrict__ ln2b,
    float* __restrict__ Cout, __half* __restrict__ Xl)
{
    __shared__ __half As[2][HBUF];
    __shared__ __half Bs[2][HBUF];
    GEMM_PROLOGUE();
    const int K = CCH, N = CCH;
    const size_t SFULL = (size_t)NROWS * CCH;
    int m0 = blockIdx.y * 128;
    int nch = K >> 5;

    uint4 ra[2], rb[2];
    auto ldg_chunk = [&](int c) {
        int k0 = c << 5;
        #pragma unroll
        for (int i = 0; i < 2; i++) {
            int idx = i * 256 + t;
            int r = idx >> 2, c8 = idx & 3;
            size_t base = (size_t)(m0 + r) * CCH + k0 + c8 * 8;
            float4 a0 = *(const float4*)&P[base];
            float4 a1 = *(const float4*)&P[base + 4];
            #pragma unroll
            for (int s = 1; s < 4; s++) {
                const float* Ps = P + (size_t)s * SFULL;
                float4 b0 = *(const float4*)&Ps[base];
                float4 b1 = *(const float4*)&Ps[base + 4];
                a0.x += b0.x; a0.y += b0.y; a0.z += b0.z; a0.w += b0.w;
                a1.x += b1.x; a1.y += b1.y; a1.z += b1.z; a1.w += b1.w;
            }
            __half2 p0 = __floats2half2_rn(a0.x, a0.y);
            __half2 p1 = __floats2half2_rn(a0.z, a0.w);
            __half2 p2 = __floats2half2_rn(a1.x, a1.y);
            __half2 p3 = __floats2half2_rn(a1.z, a1.w);
            uint4 va;
            va.x = *(uint32_t*)&p0; va.y = *(uint32_t*)&p1;
            va.z = *(uint32_t*)&p2; va.w = *(uint32_t*)&p3;
            ra[i] = va;
            rb[i] = *(const uint4*)&Bm[(size_t)r * K + k0 + c8 * 8];
        }
    };
    auto st_chunk = [&](int buf) {
        #pragma unroll
        for (int i = 0; i < 2; i++) {
            int idx = i * 256 + t;
            int r = idx >> 2, c8 = idx & 3;
            *(uint4*)&As[buf][r * LDH + c8 * 8] = ra[i];
            *(uint4*)&Bs[buf][r * LDH + c8 * 8] = rb[i];
        }
    };

    ldg_chunk(0); st_chunk(0); __syncthreads();
    for (int c = 0; c < nch; c++) {
        if (c + 1 < nch) ldg_chunk(c + 1);
        compute_chunk(acc, smem_u32(&As[c & 1][0]), smem_u32(&Bs[c & 1][0]),
                      wm, wn, lane);
        if (c + 1 < nch) { st_chunk((c + 1) & 1); __syncthreads(); }
    }
    __syncthreads();

    float2* rstats = (float2*)&As[0][0];
    float2* rmv    = (float2*)&Bs[0][0];

    int cbase = wn * 64 + tig * 2;

    float ss[4], sq[4];
    #pragma unroll
    for (int mt = 0; mt < 2; mt++)
        #pragma unroll
        for (int hh = 0; hh < 2; hh++) {
            int ii = mt * 2 + hh;
            int rl = wm * 32 + mt * 16 + hh * 8 + gid;
            size_t rowo = (size_t)(m0 + rl) * N;
            float s = 0.0f, s2 = 0.0f;
            #pragma unroll
            for (int nt = 0; nt < 8; nt++) {
                int col = cbase + nt * 8;
                float u0 = acc[mt][nt][hh*2+0] + __ldg(&bias[col]) + res[rowo + col];
                float u1 = acc[mt][nt][hh*2+1] + __ldg(&bias[col+1]) + res[rowo + col + 1];
                float2 o2; o2.x = u0; o2.y = u1;
                *(float2*)&Cout[rowo + col] = o2;
                s += u0 + u1;
                s2 = fmaf(u0, u0, fmaf(u1, u1, s2));
            }
            ss[ii] = s; sq[ii] = s2;
        }
    #pragma unroll
    for (int o = 1; o < 4; o <<= 1)
        #pragma unroll
        for (int ii = 0; ii < 4; ii++) {
            ss[ii] += __shfl_xor_sync(0xffffffffu, ss[ii], o);
            sq[ii] += __shfl_xor_sync(0xffffffffu, sq[ii], o);
        }
    if (tig == 0) {
        #pragma unroll
        for (int ii = 0; ii < 4; ii++) {
            int rl = wm * 32 + (ii >> 1) * 16 + (ii & 1) * 8 + gid;
            rstats[rl * 2 + wn] = make_float2(ss[ii], sq[ii]);
        }
    }
    __syncthreads();
    if (t < 128) {
        float2 a = rstats[t * 2 + 0];
        float2 b = rstats[t * 2 + 1];
        float s = a.x + b.x, s2 = a.y + b.y;
        float mu = s * (1.0f / 128.0f);
        float var = fmaf(-mu, mu, s2 * (1.0f / 128.0f));
        rmv[t] = make_float2(mu, rsqrtf(var + 1e-5f));
    }
    __syncthreads();

    #pragma unroll
    for (int mt = 0; mt < 2; mt++)
        #pragma unroll
        for (int hh = 0; hh < 2; hh++) {
            int rl = wm * 32 + mt * 16 + hh * 8 + gid;
            size_t rowo = (size_t)(m0 + rl) * N;
            float2 mv = rmv[rl];
            #pragma unroll
            for (int nt = 0; nt < 8; nt++) {
                int col = cbase + nt * 8;
                float u0 = acc[mt][nt][hh*2+0] + __ldg(&bias[col]) + res[rowo + col];
                float u1 = acc[mt][nt][hh*2+1] + __ldg(&bias[col+1]) + res[rowo + col + 1];
                float x0 = (u0 - mv.x) * mv.y * __ldg(&ln2w[col]) + __ldg(&ln2b[col]);
                float x1 = (u1 - mv.x) * mv.y * __ldg(&ln2w[col+1]) + __ldg(&ln2b[col+1]);
                __half2 h2 = __floats2half2_rn(x0, x1);
                *(__half2*)&Xl[rowo + col] = h2;
            }
        }
}

/* ------------- fused QKV: blockIdx.x selects output ----------------------- */
__global__ __launch_bounds__(256, 2) void gemm_qkv(
    const __half* __restrict__ A, const __half* __restrict__ Bm,
    const float* __restrict__ bq, const float* __restrict__ bk,
    const float* __restrict__ bv,
    __half* __restrict__ oq, __half* __restrict__ ok, __half* __restrict__ ov)
{
    __shared__ __half As[2][HBUF];
    __shared__ __half Bs[2][HBUF];
    GEMM_PROLOGUE();
    const int K = CCH;
    int m0 = blockIdx.y * 128;
    int n0 = blockIdx.x * 128;
    int nch = K >> 5;

    uint4 ra[2], rb[2];
    auto ldg_chunk = [&](int c) {
        int k0 = c << 5;
        #pragma unroll
        for (int i = 0; i < 2; i++) {
            int idx = i * 256 + t;
            int r = idx >> 2, c8 = idx & 3;
            ra[i] = *(const uint4*)&A[(size_t)(m0 + r) * K + k0 + c8 * 8];
            rb[i] = *(const uint4*)&Bm[(size_t)(n0 + r) * K + k0 + c8 * 8];
        }
    };
    auto st_chunk = [&](int buf) {
        #pragma unroll
        for (int i = 0; i < 2; i++) {
            int idx = i * 256 + t;
            int r = idx >> 2, c8 = idx & 3;
            *(uint4*)&As[buf][r * LDH + c8 * 8] = ra[i];
            *(uint4*)&Bs[buf][r * LDH + c8 * 8] = rb[i];
        }
    };

    ldg_chunk(0); st_chunk(0); __syncthreads();
    for (int c = 0; c < nch; c++) {
        if (c + 1 < nch) ldg_chunk(c + 1);
        compute_chunk(acc, smem_u32(&As[c & 1][0]), smem_u32(&Bs[c & 1][0]),
                      wm, wn, lane);
        if (c + 1 < nch) { st_chunk((c + 1) & 1); __syncthreads(); }
    }

    __half* Cb = (blockIdx.x == 0) ? oq : (blockIdx.x == 1) ? ok : ov;
    const float* bias = (blockIdx.x == 0) ? bq : (blockIdx.x == 1) ? bk : bv;
    float sc = (blockIdx.x == 2) ? 1.0f : SQALPHA;
    int rbase = m0 + wm * 32 + gid;
    int cbase = wn * 64 + tig * 2;
    #pragma unroll
    for (int mt = 0; mt < 2; mt++)
        #pragma unroll
        for (int hh = 0; hh < 2; hh++) {
            int row = rbase + mt * 16 + hh * 8;
            size_t rowo = (size_t)row * CCH;
            #pragma unroll
            for (int nt = 0; nt < 8; nt++) {
                int col = cbase + nt * 8;
                float u0 = (acc[mt][nt][hh*2+0] + __ldg(&bias[col])) * sc;
                float u1 = (acc[mt][nt][hh*2+1] + __ldg(&bias[col+1])) * sc;
                __half2 h2 = __floats2half2_rn(u0, u1);
                *(__half2*)&Cb[rowo + col] = h2;
            }
        }
}

/* ------------- scores GEMM: 128x64 tile, 8 m-warps, 3 CTAs/SM ------------- */
/* fp16 out (log2 domain) + fused column sums; acc = 32 fl/thread            */
__global__ __launch_bounds__(256, 3) void gemm_scores(
    const __half* __restrict__ Aq, const __half* __restrict__ Bk,
    __half* __restrict__ Cout, float* __restrict__ psum)
{
    __shared__ __half As[2][128*LDH];   /* 2 x 10 KB */
    __shared__ __half Bs[2][64*LDH];    /* 2 x  5 KB */
    int t = threadIdx.x;
    int wid = t >> 5, lane = t & 31;
    int gid = lane >> 2, tig = lane & 3;
    const int K = CCH, N = SS;
    int z = blockIdx.z;
    const __half* A = Aq + (size_t)z * SS * CCH;
    const __half* Bm = Bk + (size_t)z * SS * CCH;
    __half* Cb = Cout + (size_t)z * SS * SS;
    int m0 = blockIdx.y * 128;
    int n0 = blockIdx.x * 64;
    const int nch = 4;

    float acc[8][4];
    #pragma unroll
    for (int nt = 0; nt < 8; nt++)
        #pragma unroll
        for (int e = 0; e < 4; e++) acc[nt][e] = 0.0f;

    uint4 ra[2], rb;
    auto ldg_chunk = [&](int c) {
        int k0 = c << 5;
        #pragma unroll
        for (int i = 0; i < 2; i++) {
            int idx = i * 256 + t;
            int r = idx >> 2, c8 = idx & 3;
            ra[i] = *(const uint4*)&A[(size_t)(m0 + r) * K + k0 + c8 * 8];
        }
        int rb_r = t >> 2, rb_c = t & 3;
        rb = *(const uint4*)&Bm[(size_t)(n0 + rb_r) * K + k0 + rb_c * 8];
    };
    auto st_chunk = [&](int buf) {
        #pragma unroll
        for (int i = 0; i < 2; i++) {
            int idx = i * 256 + t;
            int r = idx >> 2, c8 = idx & 3;
            *(uint4*)&As[buf][r * LDH + c8 * 8] = ra[i];
        }
        int rb_r = t >> 2, rb_c = t & 3;
        *(uint4*)&Bs[buf][rb_r * LDH + rb_c * 8] = rb;
    };

    ldg_chunk(0); st_chunk(0); __syncthreads();
    int rA = (lane & 7) + ((lane >> 3) & 1) * 8;
    int cA = (lane >> 4) * 8;
    for (int c = 0; c < nch; c++) {
        if (c + 1 < nch) ldg_chunk(c + 1);
        uint32_t ab = smem_u32(&As[c & 1][0]);
        uint32_t bb = smem_u32(&Bs[c & 1][0]);
        #pragma unroll
        for (int s = 0; s < 2; s++) {
            int cS = s * 16 + cA;
            uint32_t af0, af1, af2, af3;
            ldsm4(af0, af1, af2, af3,
                  ab + ((uint32_t)((wid * 16 + rA) * LDH + cS) << 1));
            #pragma unroll
            for (int ntp = 0; ntp < 4; ntp++) {
                uint32_t bf0, bf1, bf2, bf3;
                ldsm4(bf0, bf1, bf2, bf3,
                      bb + ((uint32_t)((ntp * 16 + rA) * LDH + cS) << 1));
                mma_f16(acc[ntp * 2 + 0], af0, af1, af2, af3, bf0, bf2);
                mma_f16(acc[ntp * 2 + 1], af0, af1, af2, af3, bf1, bf3);
            }
        }
        if (c + 1 < nch) { st_chunk((c + 1) & 1); __syncthreads(); }
    }

    /* stats + direct store; thread covers rows gid, gid+8 of warp strip */
    __syncthreads();
    float* sstat = (float*)&As[0][0];    /* [8][64] */
    int rbase = m0 + wid * 16 + gid;
    int cbase = n0 + tig * 2;
    #pragma unroll
    for (int nt = 0; nt < 8; nt++) {
        int col = cbase + nt * 8;
        __half2 h20 = __floats2half2_rn(acc[nt][0], acc[nt][1]);  /* row gid   */
        __half2 h21 = __floats2half2_rn(acc[nt][2], acc[nt][3]);  /* row gid+8 */
        *(__half2*)&Cb[(size_t)rbase * N + col] = h20;
        *(__half2*)&Cb[(size_t)(rbase + 8) * N + col] = h21;
        uint32_t p0 = h2ex2(*(uint32_t*)&h20);
        uint32_t p1 = h2ex2(*(uint32_t*)&h21);
        float2 f0 = __half22float2(*(__half2*)&p0);
        float2 f1 = __half22float2(*(__half2*)&p1);
        float cs0 = f0.x + f1.x;
        float cs1 = f0.y + f1.y;
        #pragma unroll
        for (int o = 4; o < 32; o <<= 1) {
            cs0 += __shfl_xor_sync(0xffffffffu, cs0, o);
            cs1 += __shfl_xor_sync(0xffffffffu, cs1, o);
        }
        if (gid == 0) {
            int cl = nt * 8 + tig * 2;
            sstat[wid * 64 + cl] = cs0;
            sstat[wid * 64 + cl + 1] = cs1;
        }
    }
    __syncthreads();
    if (t < 64) {
        float s = 0.0f;
        #pragma unroll
        for (int w = 0; w < 8; w++) s += sstat[w * 64 + t];
        psum[(size_t)blockIdx.y * NROWS + (size_t)z * SS + n0 + t] = s;
    }
}

/* ------------- split-K AV: 2^(s+noff) @ vT, fp32 partials ----------------- */
__global__ __launch_bounds__(256, 2) void gemm_avsplit(
    const __half* __restrict__ Asc, const __half* __restrict__ BvT,
    const __half* __restrict__ noffh, float* __restrict__ Pout)
{
    __shared__ __half As[2][HBUF];
    __shared__ __half Bs[2][HBUF];
    GEMM_PROLOGUE();
    const int K = SS;
    int b  = blockIdx.z >> 2;
    int sp = blockIdx.z & 3;
    int kbase = sp * (SS / 4);
    const __half* A = Asc + (size_t)b * SS * SS;
    const __half* Bm = BvT + (size_t)b * SS * CCH;
    const __half* offb = noffh + (size_t)b * SS + kbase;
    int m0 = blockIdx.y * 128;
    const int nch = (SS / 4) >> 5;   /* 32 */

    uint4 ra[2], rb[2];
    auto ldg_chunk = [&](int c) {
        int k0 = c << 5;
        int c8 = t & 3;
        uint4 nf = *(const uint4*)&offb[k0 + c8 * 8];
        uint32_t* nfp = (uint32_t*)&nf;
        #pragma unroll
        for (int i = 0; i < 2; i++) {
            int idx = i * 256 + t;
            int r = idx >> 2;
            uint4 va = *(const uint4*)&A[(size_t)(m0 + r) * K + kbase + k0 + c8 * 8];
            uint32_t* hp = (uint32_t*)&va;
            #pragma unroll
            for (int j = 0; j < 4; j++) {
                __half2 sv = __hadd2(*(__half2*)&hp[j], *(__half2*)&nfp[j]);
                hp[j] = h2ex2(*(uint32_t*)&sv);
            }
            ra[i] = va;
            rb[i] = *(const uint4*)&Bm[(size_t)r * K + kbase + k0 + c8 * 8];
        }
    };
    auto st_chunk = [&](int buf) {
        #pragma unroll
        for (int i = 0; i < 2; i++) {
            int idx = i * 256 + t;
            int r = idx >> 2, c8 = idx & 3;
            *(uint4*)&As[buf][r * LDH + c8 * 8] = ra[i];
            *(uint4*)&Bs[buf][r * LDH + c8 * 8] = rb[i];
        }
    };

    ldg_chunk(0); st_chunk(0); __syncthreads();
    for (int c = 0; c < nch; c++) {
        if (c + 1 < nch) ldg_chunk(c + 1);
        compute_chunk(acc, smem_u32(&As[c & 1][0]), smem_u32(&Bs[c & 1][0]),
                      wm, wn, lane);
        if (c + 1 < nch) { st_chunk((c + 1) & 1); __syncthreads(); }
    }

    float* Cb = Pout + (size_t)sp * NROWS * CCH + (size_t)b * SS * CCH;
    int rbase = m0 + wm * 32 + gid;
    int cbase = wn * 64 + tig * 2;
    #pragma unroll
    for (int mt = 0; mt < 2; mt++)
        #pragma unroll
        for (int hh = 0; hh < 2; hh++) {
            int row = rbase + mt * 16 + hh * 8;
            size_t rowo = (size_t)row * CCH;
            #pragma unroll
            for (int nt = 0; nt < 8; nt++) {
                int col = cbase + nt * 8;
                float2 o2;
                o2.x = acc[mt][nt][hh*2+0];
                o2.y = acc[mt][nt][hh*2+1];
                *(float2*)&Cb[rowo + col] = o2;
            }
        }
}

/* ------------- MLP2 + residual + fused output transpose ------------------- */
__global__ __launch_bounds__(256, 2) void gemm_out(
    const __half* __restrict__ A, const __half* __restrict__ Bm,
    const float* __restrict__ bias, const float* __restrict__ res,
    float* __restrict__ Oout)
{
    __shared__ __align__(16) __half SH[4 * HBUF];
    __half* As0 = SH;
    __half* As1 = SH + HBUF;
    __half* Bs0 = SH + 2 * HBUF;
    __half* Bs1 = SH + 3 * HBUF;
    GEMM_PROLOGUE();
    const int K = HIDN;
    int m0 = blockIdx.y * 128;
    int nch = K >> 5;

    uint4 ra[2], rb[2];
    auto ldg_chunk = [&](int c) {
        int k0 = c << 5;
        #pragma unroll
        for (int i = 0; i < 2; i++) {
            int idx = i * 256 + t;
            int r = idx >> 2, c8 = idx & 3;
            ra[i] = *(const uint4*)&A[(size_t)(m0 + r) * K + k0 + c8 * 8];
            rb[i] = *(const uint4*)&Bm[(size_t)r * K + k0 + c8 * 8];
        }
    };
    auto st_chunk = [&](int buf) {
        __half* Ad = buf ? As1 : As0;
        __half* Bd = buf ? Bs1 : Bs0;
        #pragma unroll
        for (int i = 0; i < 2; i++) {
            int idx = i * 256 + t;
            int r = idx >> 2, c8 = idx & 3;
            *(uint4*)&Ad[r * LDH + c8 * 8] = ra[i];
            *(uint4*)&Bd[r * LDH + c8 * 8] = rb[i];
        }
    };

    ldg_chunk(0); st_chunk(0); __syncthreads();
    for (int c = 0; c < nch; c++) {
        if (c + 1 < nch) ldg_chunk(c + 1);
        compute_chunk(acc, smem_u32(c & 1 ? As1 : As0), smem_u32(c & 1 ? Bs1 : Bs0),
                      wm, wn, lane);
        if (c + 1 < nch) { st_chunk((c + 1) & 1); __syncthreads(); }
    }

    int z  = m0 / SS;
    int s0 = m0 % SS;
    float* smf = (float*)SH;      /* [64][132] fp32 per half-pass */

    #pragma unroll
    for (int hf = 0; hf < 2; hf++) {
        __syncthreads();
        #pragma unroll
        for (int mt = 0; mt < 2; mt++)
            #pragma unroll
            for (int hh = 0; hh < 2; hh++) {
                int rl = wm * 32 + mt * 16 + hh * 8 + gid;
                if ((rl >> 6) != hf) continue;
                int rr = rl & 63;
                size_t rowo = (size_t)(m0 + rl) * CCH;
                #pragma unroll
                for (int nt = 0; nt < 8; nt++) {
                    int col = wn * 64 + nt * 8 + tig * 2;
                    float u0 = gelu_exact(acc[mt][nt][hh*2+0] + __ldg(&bias[col]));
                    float u1 = gelu_exact(acc[mt][nt][hh*2+1] + __ldg(&bias[col+1]));
                    u0 += res[rowo + col];
                    u1 += res[rowo + col + 1];
                    float2 f2; f2.x = u0; f2.y = u1;
                    *(float2*)&smf[rr * 132 + col] = f2;
                }
            }
        __syncthreads();
        int cch = t >> 1, seg = t & 1;
        float* orow = Oout + ((size_t)z * CCH + cch) * SS + s0 + hf * 64 + seg * 32;
        #pragma unroll
        for (int u = 0; u < 8; u++) {
            int sb = seg * 32 + u * 4;
            float4 o;
            o.x = smf[(sb + 0) * 132 + cch];
            o.y = smf[(sb + 1) * 132 + cch];
            o.z = smf[(sb + 2) * 132 + cch];
            o.w = smf[(sb + 3) * 132 + cch];
            *(float4*)&orow[u * 4] = o;
        }
    }
}

/* ------------------------------- launch ---------------------------------- */
template<typename T>
static T* symp(const void* s) {
    void* p = nullptr;
    cudaGetSymbolAddress(&p, s);
    return (T*)p;
}

extern "C" void kernel_launch(void* const* d_in, const int* in_sizes, int n_in,
                              void* d_out, int out_size)
{
    const float* x    = (const float*)d_in[0];
    const float* ln1w = (const float*)d_in[1];
    const float* ln1b = (const float*)d_in[2];
    const float* wq   = (const float*)d_in[3];
    const float* bq   = (const float*)d_in[4];
    const float* wk   = (const float*)d_in[5];
    const float* bk   = (const float*)d_in[6];
    const float* wv   = (const float*)d_in[7];
    const float* bv   = (const float*)d_in[8];
    const float* wo   = (const float*)d_in[9];
    const float* bo   = (const float*)d_in[10];
    const float* ln2w = (const float*)d_in[11];
    const float* ln2b = (const float*)d_in[12];
    const float* w1   = (const float*)d_in[13];
    const float* b1   = (const float*)d_in[14];
    const float* w2   = (const float*)d_in[15];
    const float* b2   = (const float*)d_in[16];
    float* out = (float*)d_out;

    float*  pt    = symp<float>(g_t);
    __half* pxl   = symp<__half>(g_xl);
    __half* pq    = symp<__half>(g_q);
    __half* pk    = symp<__half>(g_k);
    __half* pv    = symp<__half>(g_v);
    __half* pvT   = symp<__half>(g_vT);
    float*  py    = symp<float>(g_y);
    __half* ph_   = symp<__half>(g_h);
    __half* psch  = symp<__half>(g_scoresh);
    float*  ppsum = symp<float>(g_psum);
    __half* poffh = symp<__half>(g_offh);
    float*  paop  = symp<float>(g_aop);
    __half* pwqkv = symp<__half>(g_wqkvT);
    __half* pwoT  = symp<__half>(g_woT);
    __half* pw1T  = symp<__half>(g_w1T);
    __half* pw2T  = symp<__half>(g_w2T);

    dim3 tb(32, 32);

    /* transpose + LN1 fused: x -> t (fp32) + xl (half) */
    ln1_fused<<<dim3(SS/32, BB), tb>>>(x, ln1w, ln1b, pt, pxl);

    /* all weight transposes in one launch */
    transpose_weights<<<dim3(8, 8, 6), tb>>>(wq, wk, wv, wo, w1, w2,
                                             pwqkv, pwoT, pw1T, pw2T);

    /* fused QKV projections -> half (q,k pre-scaled) */
    gemm_qkv<<<dim3(3, NROWS/128, 1), 256>>>(pxl, pwqkv, bq, bk, bv, pq, pk, pv);

    /* scores (log2 domain) -> fp16, 128x64 tiles, 3 CTAs/SM */
    gemm_scores<<<dim3(SS/64, SS/128, BB), 256>>>(pq, pk, psch, ppsum);

    /* reduce partial sums -> noff (half) */
    noff_k<<<NROWS/256, 256>>>(ppsum, poffh);

    /* v -> vT per batch (half) */
    transpose_h<<<dim3(CCH/32, SS/32, BB), tb>>>(pv, pvT, SS, CCH);

    /* ao partials = 2^(s + noff) @ v, split-K 4 */
    gemm_avsplit<<<dim3(1, SS/128, BB*4), 256>>>(psch, pvT, poffh, paop);

    /* y = (sum partials) @ wo + bo + t, LN2 fused -> xl */
    gemm_wo<<<dim3(1, NROWS/128, 1), 256>>>(paop, pwoT, bo, pt, ln2w, ln2b, py, pxl);

    /* h = gelu(ln2 @ w1 + b1) -> half */
    gemm_mlp1<<<dim3(HIDN/128, NROWS/128, 1), 256>>>(pxl, pw1T, b1, ph_, HIDN, CCH);

    /* out = transpose(gelu(h @ w2 + b2) + y) — final transpose fused */
    gemm_out<<<dim3(1, NROWS/128, 1), 256>>>(ph_, pw2T, b2, py, out);
}

// round 17
// speedup vs baseline: 1.1224x; 1.1224x over previous
#include <cuda_runtime.h>
#include <cuda_fp16.h>
#include <math.h>
#include <stdint.h>

#define BB 4
#define SS 4096
#define CCH 128
#define HIDN 256
#define NROWS (BB*SS)      /* 16384 */
#define SQALPHA 0.6005612044f   /* sqrt(0.25 * log2(e)) */

/* ------------ scratch (device globals: allocation-free rule) ------------- */
__device__ float  g_t   [NROWS*CCH];
__device__ __half g_xl  [NROWS*CCH];
__device__ __half g_q   [NROWS*CCH];
__device__ __half g_k   [NROWS*CCH];
__device__ __half g_v   [NROWS*CCH];
__device__ __half g_vT  [NROWS*CCH];
__device__ float  g_y   [NROWS*CCH];
__device__ __half g_h   [NROWS*HIDN];
__device__ __half g_scoresh[(size_t)BB*SS*SS];   /* 134 MB fp16 scores (log2 dom) */
__device__ float  g_psum[32*NROWS];               /* per-m-tile column sums */
__device__ __half g_offh[NROWS];                  /* -log2(l) as half */
__device__ float  g_aop [4*NROWS*CCH];            /* split-K AV partials */
__device__ __half g_wqkvT[3*CCH*CCH];
__device__ __half g_woT [CCH*CCH];
__device__ __half g_w1T [CCH*HIDN];
__device__ __half g_w2T [CCH*HIDN];

/* ------------------------- helpers --------------------------------------- */
__device__ __forceinline__ uint32_t smem_u32(const void* p) {
    uint32_t a;
    asm("{ .reg .u64 t; cvta.to.shared.u64 t, %1; cvt.u32.u64 %0, t; }"
        : "=r"(a) : "l"(p));
    return a;
}

__device__ __forceinline__ uint32_t h2ex2(uint32_t x) {
    uint32_t r;
    asm("ex2.approx.f16x2 %0, %1;" : "=r"(r) : "r"(x));
    return r;
}

__device__ __forceinline__ float gelu_exact(float v) {
    return 0.5f * v * (1.0f + erff(v * 0.70710678118654752f));
}

__device__ __forceinline__ void mma_f16(
    float* d, uint32_t a0, uint32_t a1, uint32_t a2, uint32_t a3,
    uint32_t b0, uint32_t b1)
{
    asm volatile(
        "mma.sync.aligned.m16n8k16.row.col.f32.f16.f16.f32 "
        "{%0,%1,%2,%3}, {%4,%5,%6,%7}, {%8,%9}, {%0,%1,%2,%3};"
        : "+f"(d[0]), "+f"(d[1]), "+f"(d[2]), "+f"(d[3])
        : "r"(a0), "r"(a1), "r"(a2), "r"(a3), "r"(b0), "r"(b1));
}

__device__ __forceinline__ void ldsm4(uint32_t& r0, uint32_t& r1,
                                      uint32_t& r2, uint32_t& r3, uint32_t addr)
{
    asm volatile("ldmatrix.sync.aligned.m8n8.x4.shared.b16 {%0,%1,%2,%3}, [%4];"
                 : "=r"(r0), "=r"(r1), "=r"(r2), "=r"(r3) : "r"(addr));
}

/* permuted B-row slot (within a 64-row group): row tig*16+nt*2+e -> slot
 * nt*8+tig*2+e, so each thread's acc columns become globally contiguous */
__device__ __forceinline__ int bperm(int rr) {
    return ((rr >> 1) & 7) * 8 + ((rr >> 4) & 3) * 2 + (rr & 1);
}

/* --------------------- fused transpose + LN1 ------------------------------ */
__global__ __launch_bounds__(1024) void ln1_fused(
    const float* __restrict__ x, const float* __restrict__ w,
    const float* __restrict__ b, float* __restrict__ tout,
    __half* __restrict__ xl)
{
    __shared__ float sm[32][133];
    int z  = blockIdx.y;
    int s0 = blockIdx.x * 32;
    int sx = threadIdx.x;
    int cy = threadIdx.y;
    const float* xb = x + (size_t)z * CCH * SS;
    #pragma unroll
    for (int i = 0; i < 4; i++) {
        int c = cy + 32 * i;
        sm[sx][c] = xb[(size_t)c * SS + s0 + sx];
    }
    __syncthreads();
    int row  = threadIdx.y;
    int lane = threadIdx.x;
    float4 v;
    v.x = sm[row][lane * 4 + 0];
    v.y = sm[row][lane * 4 + 1];
    v.z = sm[row][lane * 4 + 2];
    v.w = sm[row][lane * 4 + 3];
    float s = v.x + v.y + v.z + v.w;
    #pragma unroll
    for (int o = 16; o > 0; o >>= 1) s += __shfl_xor_sync(0xffffffffu, s, o);
    float mu = s * (1.0f / 128.0f);
    float dx = v.x - mu, dy = v.y - mu, dz = v.z - mu, dw = v.w - mu;
    float q = dx*dx + dy*dy + dz*dz + dw*dw;
    #pragma unroll
    for (int o = 16; o > 0; o >>= 1) q += __shfl_xor_sync(0xffffffffu, q, o);
    float rstd = rsqrtf(q * (1.0f / 128.0f) + 1e-5f);
    float4 wv = *(const float4*)&w[lane * 4];
    float4 bv = *(const float4*)&b[lane * 4];
    size_t base = ((size_t)z * SS + s0 + row) * CCH + lane * 4;
    *(float4*)&tout[base] = v;
    __half2 h01 = __floats2half2_rn(dx * rstd * wv.x + bv.x, dy * rstd * wv.y + bv.y);
    __half2 h23 = __floats2half2_rn(dz * rstd * wv.z + bv.z, dw * rstd * wv.w + bv.w);
    uint2 o2; o2.x = *(uint32_t*)&h01; o2.y = *(uint32_t*)&h23;
    *(uint2*)&xl[base] = o2;
}

/* half -> half, transposed, per batch (v -> vT) */
__global__ __launch_bounds__(1024) void transpose_h(
    const __half* __restrict__ src, __half* __restrict__ dst, int R, int Cc)
{
    __shared__ __half tile[32][34];
    size_t zo = (size_t)blockIdx.z * R * Cc;
    int c0 = blockIdx.x * 32, r0 = blockIdx.y * 32;
    int x = threadIdx.x, y = threadIdx.y;
    tile[y][x] = src[zo + (size_t)(r0 + y) * Cc + c0 + x];
    __syncthreads();
    dst[zo + (size_t)(c0 + y) * R + r0 + x] = tile[x][y];
}

/* all six weight transposes (f32 -> f16, W[K,N] -> W^T[N,K]) in ONE launch */
__global__ __launch_bounds__(1024) void transpose_weights(
    const float* __restrict__ wq, const float* __restrict__ wk,
    const float* __restrict__ wv, const float* __restrict__ wo,
    const float* __restrict__ w1, const float* __restrict__ w2,
    __half* __restrict__ dqkv, __half* __restrict__ dwo,
    __half* __restrict__ dw1, __half* __restrict__ dw2)
{
    const float* src;
    __half* dst;
    int R, Cc;
    switch (blockIdx.z) {
        case 0:  src = wq; dst = dqkv;               R = CCH;  Cc = CCH;  break;
        case 1:  src = wk; dst = dqkv + CCH*CCH;     R = CCH;  Cc = CCH;  break;
        case 2:  src = wv; dst = dqkv + 2*CCH*CCH;   R = CCH;  Cc = CCH;  break;
        case 3:  src = wo; dst = dwo;                R = CCH;  Cc = CCH;  break;
        case 4:  src = w1; dst = dw1;                R = CCH;  Cc = HIDN; break;
        default: src = w2; dst = dw2;                R = HIDN; Cc = CCH;  break;
    }
    int c0 = blockIdx.x * 32, r0 = blockIdx.y * 32;
    if (c0 >= Cc || r0 >= R) return;
    __shared__ float tile[32][33];
    int x = threadIdx.x, y = threadIdx.y;
    tile[y][x] = src[(size_t)(r0 + y) * Cc + c0 + x];
    __syncthreads();
    dst[(size_t)(c0 + y) * R + r0 + x] = __float2half_rn(tile[x][y]);
}

/* reduce 32 column-sum partials -> noff half = -log2(l) */
__global__ __launch_bounds__(256) void noff_k(
    const float* __restrict__ psum, __half* __restrict__ offh) {
    int i = blockIdx.x * 256 + threadIdx.x;
    float l = 0.0f;
    #pragma unroll
    for (int my = 0; my < 32; my++) l += psum[(size_t)my * NROWS + i];
    offh[i] = __float2half_rn(-log2f(l));
}

/* ---------------- GEMM geometry ------------------------------------------- */
#define LDH 40
#define HBUF (128*LDH)

__device__ __forceinline__ void compute_chunk(
    float acc[2][8][4], uint32_t abase, uint32_t bbase, int wm, int wn, int lane)
{
    int rA = (lane & 7) + ((lane >> 3) & 1) * 8;
    int cA = (lane >> 4) * 8;
    #pragma unroll
    for (int s = 0; s < 2; s++) {
        uint32_t af[2][4];
        #pragma unroll
        for (int mt = 0; mt < 2; mt++) {
            uint32_t addr = abase +
                ((uint32_t)((wm * 32 + mt * 16 + rA) * LDH + s * 16 + cA) << 1);
            ldsm4(af[mt][0], af[mt][1], af[mt][2], af[mt][3], addr);
        }
        #pragma unroll
        for (int ntp = 0; ntp < 4; ntp++) {
            uint32_t bf0, bf1, bf2, bf3;
            uint32_t addr = bbase +
                ((uint32_t)((wn * 64 + ntp * 16 + rA) * LDH + s * 16 + cA) << 1);
            ldsm4(bf0, bf1, bf2, bf3, addr);
            #pragma unroll
            for (int mt = 0; mt < 2; mt++) {
                mma_f16(acc[mt][ntp * 2 + 0],
                        af[mt][0], af[mt][1], af[mt][2], af[mt][3], bf0, bf2);
                mma_f16(acc[mt][ntp * 2 + 1],
                        af[mt][0], af[mt][1], af[mt][2], af[mt][3], bf1, bf3);
            }
        }
    }
}

#define GEMM_PROLOGUE()                                                         \
    int t = threadIdx.x;                                                        \
    int wid = t >> 5, lane = t & 31;                                            \
    int wm = wid & 3, wn = wid >> 2;                                            \
    int gid = lane >> 2, tig = lane & 3;                                        \
    float acc[2][8][4];                                                         \
    _Pragma("unroll")                                                           \
    for (int mt = 0; mt < 2; mt++)                                              \
        _Pragma("unroll")                                                       \
        for (int nt = 0; nt < 8; nt++)                                          \
            _Pragma("unroll")                                                   \
            for (int e = 0; e < 4; e++) acc[mt][nt][e] = 0.0f;

/* ------------- MLP1: h = gelu(A @ B^T + bias), half out ------------------- */
__global__ __launch_bounds__(256, 2) void gemm_mlp1(
    const __half* __restrict__ A, const __half* __restrict__ Bm,
    const float* __restrict__ bias, __half* __restrict__ Cout, int N, int K)
{
    __shared__ __half As[2][HBUF];
    __shared__ __half Bs[2][HBUF];
    GEMM_PROLOGUE();
    int m0 = blockIdx.y * 128;
    int n0 = blockIdx.x * 128;
    int nch = K >> 5;

    uint4 ra[2], rb[2];
    auto ldg_chunk = [&](int c) {
        int k0 = c << 5;
        #pragma unroll
        for (int i = 0; i < 2; i++) {
            int idx = i * 256 + t;
            int r = idx >> 2, c8 = idx & 3;
            ra[i] = *(const uint4*)&A[(size_t)(m0 + r) * K + k0 + c8 * 8];
            rb[i] = *(const uint4*)&Bm[(size_t)(n0 + r) * K + k0 + c8 * 8];
        }
    };
    auto st_chunk = [&](int buf) {
        #pragma unroll
        for (int i = 0; i < 2; i++) {
            int idx = i * 256 + t;
            int r = idx >> 2, c8 = idx & 3;
            *(uint4*)&As[buf][r * LDH + c8 * 8] = ra[i];
            *(uint4*)&Bs[buf][r * LDH + c8 * 8] = rb[i];
        }
    };

    ldg_chunk(0); st_chunk(0); __syncthreads();
    for (int c = 0; c < nch; c++) {
        if (c + 1 < nch) ldg_chunk(c + 1);
        compute_chunk(acc, smem_u32(&As[c & 1][0]), smem_u32(&Bs[c & 1][0]),
                      wm, wn, lane);
        if (c + 1 < nch) { st_chunk((c + 1) & 1); __syncthreads(); }
    }

    int rbase = m0 + wm * 32 + gid;
    int cbase = n0 + wn * 64 + tig * 2;
    #pragma unroll
    for (int mt = 0; mt < 2; mt++)
        #pragma unroll
        for (int hh = 0; hh < 2; hh++) {
            int row = rbase + mt * 16 + hh * 8;
            size_t rowo = (size_t)row * N;
            #pragma unroll
            for (int nt = 0; nt < 8; nt++) {
                int col = cbase + nt * 8;
                float u0 = gelu_exact(acc[mt][nt][hh*2+0] + __ldg(&bias[col]));
                float u1 = gelu_exact(acc[mt][nt][hh*2+1] + __ldg(&bias[col+1]));
                __half2 h2 = __floats2half2_rn(u0, u1);
                *(__half2*)&Cout[rowo + col] = h2;
            }
        }
}

/* ------- wo GEMM: y = (sum AV partials) @ wo^T + bo + t, LN2 fused -------- */
__global__ __launch_bounds__(256, 2) void gemm_wo(
    const float* __restrict__ P, const __half* __restrict__ Bm,
    const float* __restrict__ bias, const float* __restrict__ res,
    const float* __restrict__ ln2w, const float* __restrict__ ln2b,
    float* __restrict__ Cout, __half* __restrict__ Xl)
{
    __shared__ __half As[2][HBUF];
    __shared__ __half Bs[2][HBUF];
    GEMM_PROLOGUE();
    const int K = CCH, N = CCH;
    const size_t SFULL = (size_t)NROWS * CCH;
    int m0 = blockIdx.y * 128;
    int nch = K >> 5;

    uint4 ra[2], rb[2];
    auto ldg_chunk = [&](int c) {
        int k0 = c << 5;
        #pragma unroll
        for (int i = 0; i < 2; i++) {
            int idx = i * 256 + t;
            int r = idx >> 2, c8 = idx & 3;
            size_t base = (size_t)(m0 + r) * CCH + k0 + c8 * 8;
            float4 a0 = *(const float4*)&P[base];
            float4 a1 = *(const float4*)&P[base + 4];
            #pragma unroll
            for (int s = 1; s < 4; s++) {
                const float* Ps = P + (size_t)s * SFULL;
                float4 b0 = *(const float4*)&Ps[base];
                float4 b1 = *(const float4*)&Ps[base + 4];
                a0.x += b0.x; a0.y += b0.y; a0.z += b0.z; a0.w += b0.w;
                a1.x += b1.x; a1.y += b1.y; a1.z += b1.z; a1.w += b1.w;
            }
            __half2 p0 = __floats2half2_rn(a0.x, a0.y);
            __half2 p1 = __floats2half2_rn(a0.z, a0.w);
            __half2 p2 = __floats2half2_rn(a1.x, a1.y);
            __half2 p3 = __floats2half2_rn(a1.z, a1.w);
            uint4 va;
            va.x = *(uint32_t*)&p0; va.y = *(uint32_t*)&p1;
            va.z = *(uint32_t*)&p2; va.w = *(uint32_t*)&p3;
            ra[i] = va;
            rb[i] = *(const uint4*)&Bm[(size_t)r * K + k0 + c8 * 8];
        }
    };
    auto st_chunk = [&](int buf) {
        #pragma unroll
        for (int i = 0; i < 2; i++) {
            int idx = i * 256 + t;
            int r = idx >> 2, c8 = idx & 3;
            *(uint4*)&As[buf][r * LDH + c8 * 8] = ra[i];
            *(uint4*)&Bs[buf][r * LDH + c8 * 8] = rb[i];
        }
    };

    ldg_chunk(0); st_chunk(0); __syncthreads();
    for (int c = 0; c < nch; c++) {
        if (c + 1 < nch) ldg_chunk(c + 1);
        compute_chunk(acc, smem_u32(&As[c & 1][0]), smem_u32(&Bs[c & 1][0]),
                      wm, wn, lane);
        if (c + 1 < nch) { st_chunk((c + 1) & 1); __syncthreads(); }
    }
    __syncthreads();

    float2* rstats = (float2*)&As[0][0];
    float2* rmv    = (float2*)&Bs[0][0];

    int cbase = wn * 64 + tig * 2;

    float ss[4], sq[4];
    #pragma unroll
    for (int mt = 0; mt < 2; mt++)
        #pragma unroll
        for (int hh = 0; hh < 2; hh++) {
            int ii = mt * 2 + hh;
            int rl = wm * 32 + mt * 16 + hh * 8 + gid;
            size_t rowo = (size_t)(m0 + rl) * N;
            float s = 0.0f, s2 = 0.0f;
            #pragma unroll
            for (int nt = 0; nt < 8; nt++) {
                int col = cbase + nt * 8;
                float u0 = acc[mt][nt][hh*2+0] + __ldg(&bias[col]) + res[rowo + col];
                float u1 = acc[mt][nt][hh*2+1] + __ldg(&bias[col+1]) + res[rowo + col + 1];
                float2 o2; o2.x = u0; o2.y = u1;
                *(float2*)&Cout[rowo + col] = o2;
                s += u0 + u1;
                s2 = fmaf(u0, u0, fmaf(u1, u1, s2));
            }
            ss[ii] = s; sq[ii] = s2;
        }
    #pragma unroll
    for (int o = 1; o < 4; o <<= 1)
        #pragma unroll
        for (int ii = 0; ii < 4; ii++) {
            ss[ii] += __shfl_xor_sync(0xffffffffu, ss[ii], o);
            sq[ii] += __shfl_xor_sync(0xffffffffu, sq[ii], o);
        }
    if (tig == 0) {
        #pragma unroll
        for (int ii = 0; ii < 4; ii++) {
            int rl = wm * 32 + (ii >> 1) * 16 + (ii & 1) * 8 + gid;
            rstats[rl * 2 + wn] = make_float2(ss[ii], sq[ii]);
        }
    }
    __syncthreads();
    if (t < 128) {
        float2 a = rstats[t * 2 + 0];
        float2 b = rstats[t * 2 + 1];
        float s = a.x + b.x, s2 = a.y + b.y;
        float mu = s * (1.0f / 128.0f);
        float var = fmaf(-mu, mu, s2 * (1.0f / 128.0f));
        rmv[t] = make_float2(mu, rsqrtf(var + 1e-5f));
    }
    __syncthreads();

    #pragma unroll
    for (int mt = 0; mt < 2; mt++)
        #pragma unroll
        for (int hh = 0; hh < 2; hh++) {
            int rl = wm * 32 + mt * 16 + hh * 8 + gid;
            size_t rowo = (size_t)(m0 + rl) * N;
            float2 mv = rmv[rl];
            #pragma unroll
            for (int nt = 0; nt < 8; nt++) {
                int col = cbase + nt * 8;
                float u0 = acc[mt][nt][hh*2+0] + __ldg(&bias[col]) + res[rowo + col];
                float u1 = acc[mt][nt][hh*2+1] + __ldg(&bias[col+1]) + res[rowo + col + 1];
                float x0 = (u0 - mv.x) * mv.y * __ldg(&ln2w[col]) + __ldg(&ln2b[col]);
                float x1 = (u1 - mv.x) * mv.y * __ldg(&ln2w[col+1]) + __ldg(&ln2b[col+1]);
                __half2 h2 = __floats2half2_rn(x0, x1);
                *(__half2*)&Xl[rowo + col] = h2;
            }
        }
}

/* ------------- fused QKV: blockIdx.x selects output ----------------------- */
__global__ __launch_bounds__(256, 2) void gemm_qkv(
    const __half* __restrict__ A, const __half* __restrict__ Bm,
    const float* __restrict__ bq, const float* __restrict__ bk,
    const float* __restrict__ bv,
    __half* __restrict__ oq, __half* __restrict__ ok, __half* __restrict__ ov)
{
    __shared__ __half As[2][HBUF];
    __shared__ __half Bs[2][HBUF];
    GEMM_PROLOGUE();
    const int K = CCH;
    int m0 = blockIdx.y * 128;
    int n0 = blockIdx.x * 128;
    int nch = K >> 5;

    uint4 ra[2], rb[2];
    auto ldg_chunk = [&](int c) {
        int k0 = c << 5;
        #pragma unroll
        for (int i = 0; i < 2; i++) {
            int idx = i * 256 + t;
            int r = idx >> 2, c8 = idx & 3;
            ra[i] = *(const uint4*)&A[(size_t)(m0 + r) * K + k0 + c8 * 8];
            rb[i] = *(const uint4*)&Bm[(size_t)(n0 + r) * K + k0 + c8 * 8];
        }
    };
    auto st_chunk = [&](int buf) {
        #pragma unroll
        for (int i = 0; i < 2; i++) {
            int idx = i * 256 + t;
            int r = idx >> 2, c8 = idx & 3;
            *(uint4*)&As[buf][r * LDH + c8 * 8] = ra[i];
            *(uint4*)&Bs[buf][r * LDH + c8 * 8] = rb[i];
        }
    };

    ldg_chunk(0); st_chunk(0); __syncthreads();
    for (int c = 0; c < nch; c++) {
        if (c + 1 < nch) ldg_chunk(c + 1);
        compute_chunk(acc, smem_u32(&As[c & 1][0]), smem_u32(&Bs[c & 1][0]),
                      wm, wn, lane);
        if (c + 1 < nch) { st_chunk((c + 1) & 1); __syncthreads(); }
    }

    __half* Cb = (blockIdx.x == 0) ? oq : (blockIdx.x == 1) ? ok : ov;
    const float* bias = (blockIdx.x == 0) ? bq : (blockIdx.x == 1) ? bk : bv;
    float sc = (blockIdx.x == 2) ? 1.0f : SQALPHA;
    int rbase = m0 + wm * 32 + gid;
    int cbase = wn * 64 + tig * 2;
    #pragma unroll
    for (int mt = 0; mt < 2; mt++)
        #pragma unroll
        for (int hh = 0; hh < 2; hh++) {
            int row = rbase + mt * 16 + hh * 8;
            size_t rowo = (size_t)row * CCH;
            #pragma unroll
            for (int nt = 0; nt < 8; nt++) {
                int col = cbase + nt * 8;
                float u0 = (acc[mt][nt][hh*2+0] + __ldg(&bias[col])) * sc;
                float u1 = (acc[mt][nt][hh*2+1] + __ldg(&bias[col+1])) * sc;
                __half2 h2 = __floats2half2_rn(u0, u1);
                *(__half2*)&Cb[rowo + col] = h2;
            }
        }
}

/* ------------- scores GEMM: fp16 out (log2 dom), permuted-B epilogue ------ */
/* B rows permuted in smem so each thread owns 16 CONTIGUOUS output columns
 * (cols wn*64 + tig*16 .. +15) -> 2x STG.128 per row. Fused column sums.    */
__global__ __launch_bounds__(256, 2) void gemm_scores(
    const __half* __restrict__ Aq, const __half* __restrict__ Bk,
    __half* __restrict__ Cout, float* __restrict__ psum)
{
    __shared__ __half As[2][HBUF];
    __shared__ __half Bs[2][HBUF];
    GEMM_PROLOGUE();
    const int K = CCH, N = SS;
    int z = blockIdx.z;
    const __half* A = Aq + (size_t)z * SS * CCH;
    const __half* Bm = Bk + (size_t)z * SS * CCH;
    __half* Cb = Cout + (size_t)z * SS * SS;
    int m0 = blockIdx.y * 128;
    int n0 = blockIdx.x * 128;
    int nch = K >> 5;

    uint4 ra[2], rb[2];
    auto ldg_chunk = [&](int c) {
        int k0 = c << 5;
        #pragma unroll
        for (int i = 0; i < 2; i++) {
            int idx = i * 256 + t;
            int r = idx >> 2, c8 = idx & 3;
            ra[i] = *(const uint4*)&A[(size_t)(m0 + r) * K + k0 + c8 * 8];
            rb[i] = *(const uint4*)&Bm[(size_t)(n0 + r) * K + k0 + c8 * 8];
        }
    };
    auto st_chunk = [&](int buf) {
        #pragma unroll
        for (int i = 0; i < 2; i++) {
            int idx = i * 256 + t;
            int r = idx >> 2, c8 = idx & 3;
            *(uint4*)&As[buf][r * LDH + c8 * 8] = ra[i];
            int grp = r >> 6, rr = r & 63;
            int br = grp * 64 + bperm(rr);
            *(uint4*)&Bs[buf][br * LDH + c8 * 8] = rb[i];
        }
    };

    ldg_chunk(0); st_chunk(0); __syncthreads();
    for (int c = 0; c < nch; c++) {
        if (c + 1 < nch) ldg_chunk(c + 1);
        compute_chunk(acc, smem_u32(&As[c & 1][0]), smem_u32(&Bs[c & 1][0]),
                      wm, wn, lane);
        if (c + 1 < nch) { st_chunk((c + 1) & 1); __syncthreads(); }
    }

    __syncthreads();
    float* sstat = (float*)&As[0][0];    /* [4][128] */

    /* thread owns global cols cb..cb+15 (contiguous), 4 rows */
    int rbase = m0 + wm * 32 + gid;
    int cb = n0 + wn * 64 + tig * 16;
    float cs[16];
    #pragma unroll
    for (int j = 0; j < 16; j++) cs[j] = 0.0f;

    #pragma unroll
    for (int mt = 0; mt < 2; mt++)
        #pragma unroll
        for (int hh = 0; hh < 2; hh++) {
            int row = rbase + mt * 16 + hh * 8;
            uint32_t pkr[8];
            #pragma unroll
            for (int nt = 0; nt < 8; nt++) {
                __half2 h2 = __floats2half2_rn(acc[mt][nt][hh*2+0],
                                               acc[mt][nt][hh*2+1]);
                pkr[nt] = *(uint32_t*)&h2;
                uint32_t pe = h2ex2(pkr[nt]);
                float2 pf = __half22float2(*(__half2*)&pe);
                cs[nt*2] += pf.x;
                cs[nt*2+1] += pf.y;
            }
            __half* dr = &Cb[(size_t)row * N + cb];
            uint4 v0; v0.x = pkr[0]; v0.y = pkr[1]; v0.z = pkr[2]; v0.w = pkr[3];
            uint4 v1; v1.x = pkr[4]; v1.y = pkr[5]; v1.z = pkr[6]; v1.w = pkr[7];
            *(uint4*)&dr[0] = v0;
            *(uint4*)&dr[8] = v1;
        }
    #pragma unroll
    for (int j = 0; j < 16; j++) {
        #pragma unroll
        for (int o = 4; o < 32; o <<= 1)
            cs[j] += __shfl_xor_sync(0xffffffffu, cs[j], o);
    }
    if (gid == 0) {
        #pragma unroll
        for (int j = 0; j < 16; j++)
            sstat[wm * 128 + wn * 64 + tig * 16 + j] = cs[j];
    }
    __syncthreads();
    if (t < 128) {
        float s = sstat[t] + sstat[128 + t] + sstat[256 + t] + sstat[384 + t];
        psum[(size_t)blockIdx.y * NROWS + (size_t)z * SS + n0 + t] = s;
    }
}

/* ------------- split-K AV: 2^(s+noff) @ vT, permuted-B epilogue ----------- */
__global__ __launch_bounds__(256, 2) void gemm_avsplit(
    const __half* __restrict__ Asc, const __half* __restrict__ BvT,
    const __half* __restrict__ noffh, float* __restrict__ Pout)
{
    __shared__ __half As[2][HBUF];
    __shared__ __half Bs[2][HBUF];
    GEMM_PROLOGUE();
    const int K = SS;
    int b  = blockIdx.z >> 2;
    int sp = blockIdx.z & 3;
    int kbase = sp * (SS / 4);
    const __half* A = Asc + (size_t)b * SS * SS;
    const __half* Bm = BvT + (size_t)b * SS * CCH;
    const __half* offb = noffh + (size_t)b * SS + kbase;
    int m0 = blockIdx.y * 128;
    const int nch = (SS / 4) >> 5;   /* 32 */

    uint4 ra[2], rb[2];
    auto ldg_chunk = [&](int c) {
        int k0 = c << 5;
        int c8 = t & 3;
        uint4 nf = *(const uint4*)&offb[k0 + c8 * 8];
        uint32_t* nfp = (uint32_t*)&nf;
        #pragma unroll
        for (int i = 0; i < 2; i++) {
            int idx = i * 256 + t;
            int r = idx >> 2;
            uint4 va = *(const uint4*)&A[(size_t)(m0 + r) * K + kbase + k0 + c8 * 8];
            uint32_t* hp = (uint32_t*)&va;
            #pragma unroll
            for (int j = 0; j < 4; j++) {
                __half2 sv = __hadd2(*(__half2*)&hp[j], *(__half2*)&nfp[j]);
                hp[j] = h2ex2(*(uint32_t*)&sv);
            }
            ra[i] = va;
            rb[i] = *(const uint4*)&Bm[(size_t)r * K + kbase + k0 + c8 * 8];
        }
    };
    auto st_chunk = [&](int buf) {
        #pragma unroll
        for (int i = 0; i < 2; i++) {
            int idx = i * 256 + t;
            int r = idx >> 2, c8 = idx & 3;
            *(uint4*)&As[buf][r * LDH + c8 * 8] = ra[i];
            int grp = r >> 6, rr = r & 63;
            int br = grp * 64 + bperm(rr);
            *(uint4*)&Bs[buf][br * LDH + c8 * 8] = rb[i];
        }
    };

    ldg_chunk(0); st_chunk(0); __syncthreads();
    for (int c = 0; c < nch; c++) {
        if (c + 1 < nch) ldg_chunk(c + 1);
        compute_chunk(acc, smem_u32(&As[c & 1][0]), smem_u32(&Bs[c & 1][0]),
                      wm, wn, lane);
        if (c + 1 < nch) { st_chunk((c + 1) & 1); __syncthreads(); }
    }

    /* thread owns 16 contiguous cols: wn*64 + tig*16 .. +15 */
    float* Cb = Pout + (size_t)sp * NROWS * CCH + (size_t)b * SS * CCH;
    int rbase = m0 + wm * 32 + gid;
    int cb = wn * 64 + tig * 16;
    #pragma unroll
    for (int mt = 0; mt < 2; mt++)
        #pragma unroll
        for (int hh = 0; hh < 2; hh++) {
            int row = rbase + mt * 16 + hh * 8;
            float* dr = &Cb[(size_t)row * CCH + cb];
            #pragma unroll
            for (int ntp = 0; ntp < 4; ntp++) {
                float4 o;
                o.x = acc[mt][ntp*2+0][hh*2+0];
                o.y = acc[mt][ntp*2+0][hh*2+1];
                o.z = acc[mt][ntp*2+1][hh*2+0];
                o.w = acc[mt][ntp*2+1][hh*2+1];
                *(float4*)&dr[ntp * 4] = o;
            }
        }
}

/* ------------- MLP2 + residual + fused output transpose ------------------- */
__global__ __launch_bounds__(256, 2) void gemm_out(
    const __half* __restrict__ A, const __half* __restrict__ Bm,
    const float* __restrict__ bias, const float* __restrict__ res,
    float* __restrict__ Oout)
{
    __shared__ __align__(16) __half SH[4 * HBUF];
    __half* As0 = SH;
    __half* As1 = SH + HBUF;
    __half* Bs0 = SH + 2 * HBUF;
    __half* Bs1 = SH + 3 * HBUF;
    GEMM_PROLOGUE();
    const int K = HIDN;
    int m0 = blockIdx.y * 128;
    int nch = K >> 5;

    uint4 ra[2], rb[2];
    auto ldg_chunk = [&](int c) {
        int k0 = c << 5;
        #pragma unroll
        for (int i = 0; i < 2; i++) {
            int idx = i * 256 + t;
            int r = idx >> 2, c8 = idx & 3;
            ra[i] = *(const uint4*)&A[(size_t)(m0 + r) * K + k0 + c8 * 8];
            rb[i] = *(const uint4*)&Bm[(size_t)r * K + k0 + c8 * 8];
        }
    };
    auto st_chunk = [&](int buf) {
        __half* Ad = buf ? As1 : As0;
        __half* Bd = buf ? Bs1 : Bs0;
        #pragma unroll
        for (int i = 0; i < 2; i++) {
            int idx = i * 256 + t;
            int r = idx >> 2, c8 = idx & 3;
            *(uint4*)&Ad[r * LDH + c8 * 8] = ra[i];
            *(uint4*)&Bd[r * LDH + c8 * 8] = rb[i];
        }
    };

    ldg_chunk(0); st_chunk(0); __syncthreads();
    for (int c = 0; c < nch; c++) {
        if (c + 1 < nch) ldg_chunk(c + 1);
        compute_chunk(acc, smem_u32(c & 1 ? As1 : As0), smem_u32(c & 1 ? Bs1 : Bs0),
                      wm, wn, lane);
        if (c + 1 < nch) { st_chunk((c + 1) & 1); __syncthreads(); }
    }

    int z  = m0 / SS;
    int s0 = m0 % SS;
    float* smf = (float*)SH;      /* [64][132] fp32 per half-pass */

    #pragma unroll
    for (int hf = 0; hf < 2; hf++) {
        __syncthreads();
        #pragma unroll
        for (int mt = 0; mt < 2; mt++)
            #pragma unroll
            for (int hh = 0; hh < 2; hh++) {
                int rl = wm * 32 + mt * 16 + hh * 8 + gid;
                if ((rl >> 6) != hf) continue;
                int rr = rl & 63;
                size_t rowo = (size_t)(m0 + rl) * CCH;
                #pragma unroll
                for (int nt = 0; nt < 8; nt++) {
                    int col = wn * 64 + nt * 8 + tig * 2;
                    float u0 = gelu_exact(acc[mt][nt][hh*2+0] + __ldg(&bias[col]));
                    float u1 = gelu_exact(acc[mt][nt][hh*2+1] + __ldg(&bias[col+1]));
                    u0 += res[rowo + col];
                    u1 += res[rowo + col + 1];
                    float2 f2; f2.x = u0; f2.y = u1;
                    *(float2*)&smf[rr * 132 + col] = f2;
                }
            }
        __syncthreads();
        int cch = t >> 1, seg = t & 1;
        float* orow = Oout + ((size_t)z * CCH + cch) * SS + s0 + hf * 64 + seg * 32;
        #pragma unroll
        for (int u = 0; u < 8; u++) {
            int sb = seg * 32 + u * 4;
            float4 o;
            o.x = smf[(sb + 0) * 132 + cch];
            o.y = smf[(sb + 1) * 132 + cch];
            o.z = smf[(sb + 2) * 132 + cch];
            o.w = smf[(sb + 3) * 132 + cch];
            *(float4*)&orow[u * 4] = o;
        }
    }
}

/* ------------------------------- launch ---------------------------------- */
template<typename T>
static T* symp(const void* s) {
    void* p = nullptr;
    cudaGetSymbolAddress(&p, s);
    return (T*)p;
}

extern "C" void kernel_launch(void* const* d_in, const int* in_sizes, int n_in,
                              void* d_out, int out_size)
{
    const float* x    = (const float*)d_in[0];
    const float* ln1w = (const float*)d_in[1];
    const float* ln1b = (const float*)d_in[2];
    const float* wq   = (const float*)d_in[3];
    const float* bq   = (const float*)d_in[4];
    const float* wk   = (const float*)d_in[5];
    const float* bk   = (const float*)d_in[6];
    const float* wv   = (const float*)d_in[7];
    const float* bv   = (const float*)d_in[8];
    const float* wo   = (const float*)d_in[9];
    const float* bo   = (const float*)d_in[10];
    const float* ln2w = (const float*)d_in[11];
    const float* ln2b = (const float*)d_in[12];
    const float* w1   = (const float*)d_in[13];
    const float* b1   = (const float*)d_in[14];
    const float* w2   = (const float*)d_in[15];
    const float* b2   = (const float*)d_in[16];
    float* out = (float*)d_out;

    float*  pt    = symp<float>(g_t);
    __half* pxl   = symp<__half>(g_xl);
    __half* pq    = symp<__half>(g_q);
    __half* pk    = symp<__half>(g_k);
    __half* pv    = symp<__half>(g_v);
    __half* pvT   = symp<__half>(g_vT);
    float*  py    = symp<float>(g_y);
    __half* ph_   = symp<__half>(g_h);
    __half* psch  = symp<__half>(g_scoresh);
    float*  ppsum = symp<float>(g_psum);
    __half* poffh = symp<__half>(g_offh);
    float*  paop  = symp<float>(g_aop);
    __half* pwqkv = symp<__half>(g_wqkvT);
    __half* pwoT  = symp<__half>(g_woT);
    __half* pw1T  = symp<__half>(g_w1T);
    __half* pw2T  = symp<__half>(g_w2T);

    dim3 tb(32, 32);

    /* transpose + LN1 fused: x -> t (fp32) + xl (half) */
    ln1_fused<<<dim3(SS/32, BB), tb>>>(x, ln1w, ln1b, pt, pxl);

    /* all weight transposes in one launch */
    transpose_weights<<<dim3(8, 8, 6), tb>>>(wq, wk, wv, wo, w1, w2,
                                             pwqkv, pwoT, pw1T, pw2T);

    /* fused QKV projections -> half (q,k pre-scaled) */
    gemm_qkv<<<dim3(3, NROWS/128, 1), 256>>>(pxl, pwqkv, bq, bk, bv, pq, pk, pv);

    /* scores (log2 domain) -> fp16, permuted-B packed stores + column sums */
    gemm_scores<<<dim3(SS/128, SS/128, BB), 256>>>(pq, pk, psch, ppsum);

    /* reduce partial sums -> noff (half) */
    noff_k<<<NROWS/256, 256>>>(ppsum, poffh);

    /* v -> vT per batch (half) */
    transpose_h<<<dim3(CCH/32, SS/32, BB), tb>>>(pv, pvT, SS, CCH);

    /* ao partials = 2^(s + noff) @ v, split-K 4, permuted-B packed stores */
    gemm_avsplit<<<dim3(1, SS/128, BB*4), 256>>>(psch, pvT, poffh, paop);

    /* y = (sum partials) @ wo + bo + t, LN2 fused -> xl */
    gemm_wo<<<dim3(1, NROWS/128, 1), 256>>>(paop, pwoT, bo, pt, ln2w, ln2b, py, pxl);

    /* h = gelu(ln2 @ w1 + b1) -> half */
    gemm_mlp1<<<dim3(HIDN/128, NROWS/128, 1), 256>>>(pxl, pw1T, b1, ph_, HIDN, CCH);

    /* out = transpose(gelu(h @ w2 + b2) + y) — final transpose fused */
    gemm_out<<<dim3(1, NROWS/128, 1), 256>>>(ph_, pw2T, b2, py, out);
}